// round 2
// baseline (speedup 1.0000x reference)
#include <cuda_runtime.h>
#include <math.h>

// ---------------- problem constants ----------------
#define NB   64
#define LL   2048
#define MS   12
#define DD   128
#define PP   16
#define SSTR 8
#define TT   256
#define KC   5
#define DR   32
#define NLB  3
#define NMB  2
#define DI   256
#define DCV  4
#define DSN  16
#define RKD  8
#define CC   18
#define BMR  768     // NB*MS
#define BT   16384   // NB*TT

// ---------------- scratch (device globals, no allocs) ----------------
__device__ float g_uA [BMR*DD*TT];   // u ping
__device__ float g_uB [BMR*DD*TT];   // u pong
__device__ float g_wA [BMR*DD*TT];   // w ping
__device__ float g_wB [BMR*DD*TT];   // w pong
__device__ float g_s2 [BMR*2*DD];    // per-(bm,bn) t-sum partials
__device__ float g_a  [BMR*DD];
__device__ float g_x2 [BT*DD];       // [b*T+t][d]
__device__ float g_xz [BT*2*DI];     // [bt][e]
__device__ float g_xc [BT*DI];       // [bt][c]
__device__ float g_dbl[BT*40];       // [bt][k]  (only k>=8 = B,C used by scan)
__device__ float g_dt [BT*DI];
__device__ float g_y  [BT*DI];
__device__ float g_out[BT*DD];

// ---------------- stage 1: embedding conv ----------------
__global__ void k_emb(const float* __restrict__ xin,
                      const float* __restrict__ w,
                      const float* __restrict__ bias) {
    __shared__ float srow[LL];
    __shared__ float sw[DD*PP];
    __shared__ float sb[DD];
    int bm = blockIdx.x;
    int b = bm / MS, m = bm % MS;
    const float* xp = xin + (size_t)b * (LL*MS) + m;
    for (int l = threadIdx.x; l < LL; l += blockDim.x) srow[l] = xp[(size_t)l * MS];
    for (int i = threadIdx.x; i < DD*PP; i += blockDim.x) sw[i] = w[i];
    for (int i = threadIdx.x; i < DD; i += blockDim.x) sb[i] = bias[i];
    __syncthreads();
    int t = threadIdx.x;            // 0..255
    int base = t * SSTR - 4;        // pad 4 left
    float* outp = g_uA + (size_t)bm * (DD*TT);
    for (int d = 0; d < DD; d++) {
        float acc = sb[d];
        #pragma unroll
        for (int p = 0; p < PP; p++) {
            int l = base + p;
            if (l >= 0 && l < LL) acc += sw[d*PP + p] * srow[l];
        }
        outp[d*TT + t] = acc;
    }
}

// ---------------- fused block kernel ----------------
// Per (bm, bn-tile of 128 t):
//  (1) u_cur = u_in (+ w_prev * a_prev if apply); write u_cur interior to u_out
//  (2) v = gelu(dwconv5(u_cur))        (computed tile-wise into smem)
//  (3) w = pw_w @ v + pw_b  -> w_out   (128x128x128 GEMM per tile)
//  (4) per-tile t-sums of w -> g_s2 (for SE)
__global__ void __launch_bounds__(256) k_block(
    const float* __restrict__ u_in, const float* __restrict__ w_prev,
    const float* __restrict__ a_prev, float* __restrict__ u_out,
    float* __restrict__ w_out, float* __restrict__ s_out,
    const float* __restrict__ dww, const float* __restrict__ dwb,
    const float* __restrict__ pwA, const float* __restrict__ pwb,
    int apply)
{
    __shared__ __align__(16) float As[16][128];
    __shared__ __align__(16) float Bs[16][128];
    __shared__ float su[16][132];     // u_cur staging (t halo 2 each side)
    __shared__ float sdw[DD*KC];
    __shared__ float sdb[DD];
    __shared__ float sa[DD];

    int bm = blockIdx.y;
    int bn = blockIdx.x;              // 0 or 1
    int t0 = bn * 128;
    int tid = threadIdx.x;
    const float* up = u_in  + (size_t)bm * (DD*TT);
    const float* wp = w_prev + (size_t)bm * (DD*TT);
    float* uo = u_out + (size_t)bm * (DD*TT);
    float* wo = w_out + (size_t)bm * (DD*TT);

    for (int i = tid; i < DD*KC; i += 256) sdw[i] = dww[i];
    for (int i = tid; i < DD; i += 256) {
        sdb[i] = dwb[i];
        sa[i]  = apply ? a_prev[bm*DD + i] : 0.0f;
    }

    int lr = tid >> 2, lk = (tid & 3) << 2;
    int tr = tid >> 4, tc = tid & 15;
    float acc[8][8];
    #pragma unroll
    for (int i = 0; i < 8; i++)
        #pragma unroll
        for (int j = 0; j < 8; j++) acc[i][j] = 0.0f;

    for (int kk = 0; kk < DD; kk += 16) {
        __syncthreads();   // prior iter done reading As/Bs/su
        // ---- phase 1: load A tile; build u_cur staging ----
        {
            float4 a0 = *(const float4*)&pwA[lr*DD + kk + lk];
            float4 a1 = *(const float4*)&pwA[(64+lr)*DD + kk + lk];
            As[lk+0][lr] = a0.x; As[lk+1][lr] = a0.y; As[lk+2][lr] = a0.z; As[lk+3][lr] = a0.w;
            As[lk+0][64+lr] = a1.x; As[lk+1][64+lr] = a1.y; As[lk+2][64+lr] = a1.z; As[lk+3][64+lr] = a1.w;
            for (int i = tid; i < 16*132; i += 256) {
                int dr = i / 132, j = i - dr*132;
                int d = kk + dr;
                int t = t0 + j - 2;
                float val = 0.0f;
                if (t >= 0 && t < TT) {
                    val = up[d*TT + t];
                    if (apply) {
                        val += wp[d*TT + t] * sa[d];
                        if (j >= 2 && j < 130) uo[d*TT + t] = val;
                    }
                }
                su[dr][j] = val;
            }
        }
        __syncthreads();
        // ---- phase 2: dwconv + gelu -> Bs ----
        {
            int dr = tid >> 4;     // 0..15
            int c0 = tid & 15;     // 0..15
            int d = kk + dr;
            float w0 = sdw[d*KC+0], w1 = sdw[d*KC+1], w2 = sdw[d*KC+2],
                  w3 = sdw[d*KC+3], w4 = sdw[d*KC+4];
            float bb = sdb[d];
            #pragma unroll
            for (int m = 0; m < 8; m++) {
                int c = c0 + m*16;
                float a = bb + w0*su[dr][c] + w1*su[dr][c+1] + w2*su[dr][c+2]
                             + w3*su[dr][c+3] + w4*su[dr][c+4];
                Bs[dr][c] = 0.5f * a * (1.0f + erff(a * 0.7071067811865475f));
            }
        }
        __syncthreads();
        // ---- phase 3: FMA ----
        #pragma unroll
        for (int k = 0; k < 16; k++) {
            float ra[8], rb[8];
            *(float4*)&ra[0] = *(const float4*)&As[k][tr*4];
            *(float4*)&ra[4] = *(const float4*)&As[k][64 + tr*4];
            *(float4*)&rb[0] = *(const float4*)&Bs[k][tc*4];
            *(float4*)&rb[4] = *(const float4*)&Bs[k][64 + tc*4];
            #pragma unroll
            for (int i = 0; i < 8; i++)
                #pragma unroll
                for (int j = 0; j < 8; j++) acc[i][j] += ra[i]*rb[j];
        }
    }
    // ---- epilogue: bias, store w, t-sum partials ----
    float* red = &su[0][0];    // reuse (2112 >= 2048); FMA never reads su
    float rs[8];
    #pragma unroll
    for (int i = 0; i < 8; i++) {
        int r = (i < 4) ? (tr*4 + i) : (64 + tr*4 + i - 4);
        float bv = pwb[r];
        float s = 0.0f;
        #pragma unroll
        for (int j = 0; j < 8; j++) {
            int cc = (j < 4) ? (tc*4 + j) : (64 + tc*4 + j - 4);
            float val = acc[i][j] + bv;
            wo[r*TT + t0 + cc] = val;
            s += val;
        }
        rs[i] = s;
    }
    __syncthreads();
    #pragma unroll
    for (int i = 0; i < 8; i++) {
        int r = (i < 4) ? (tr*4 + i) : (64 + tr*4 + i - 4);
        red[r*16 + tc] = rs[i];
    }
    __syncthreads();
    if (tid < DD) {
        float s = 0.0f;
        #pragma unroll
        for (int j = 0; j < 16; j++) s += red[tid*16 + j];
        s_out[(bm*2 + bn)*DD + tid] = s;
    }
}

// ---------------- SE MLP (reads t-sum partials) ----------------
__global__ void k_se(const float* __restrict__ w1, const float* __restrict__ b1,
                     const float* __restrict__ w2, const float* __restrict__ b2) {
    __shared__ float ss[DD];
    __shared__ float hh[DR];
    int bm = blockIdx.x, tid = threadIdx.x;
    ss[tid] = (g_s2[(bm*2+0)*DD + tid] + g_s2[(bm*2+1)*DD + tid]) * (1.0f/TT);
    __syncthreads();
    if (tid < DR) {
        float acc = b1[tid];
        for (int d = 0; d < DD; d++) acc += w1[tid*DD + d] * ss[d];
        hh[tid] = fmaxf(acc, 0.0f);
    }
    __syncthreads();
    float acc = b2[tid];
    #pragma unroll
    for (int j = 0; j < DR; j++) acc += w2[tid*DR + j] * hh[j];
    g_a[bm*DD + tid] = 1.0f / (1.0f + __expf(-acc));
}

// ---------------- final apply + sensor mean + transpose to [bt][d] ----------------
__global__ void k_smean2(const float* __restrict__ u, const float* __restrict__ w,
                         const float* __restrict__ a) {
    __shared__ float sm[32][257];
    int b = blockIdx.x, d0 = blockIdx.y * 32;
    int tid = threadIdx.x;   // 256
    for (int dd = 0; dd < 32; dd++) {
        int d = d0 + dd;
        float s = 0.0f;
        #pragma unroll
        for (int m = 0; m < MS; m++) {
            int bm = b*MS + m;
            size_t o = (size_t)bm*(DD*TT) + d*TT + tid;
            s += u[o] + w[o] * a[bm*DD + d];
        }
        sm[dd][tid] = s * (1.0f/MS);
    }
    __syncthreads();
    int t2 = tid >> 5, dd2 = tid & 31;
    for (int tt = t2; tt < TT; tt += 8)
        g_x2[(size_t)(b*TT + tt)*DD + d0 + dd2] = sm[dd2][tt];
}

// ---------------- generic NT SGEMM for mamba projections ----------------
__global__ void __launch_bounds__(256) k_gemm_nt(int mode, const float* __restrict__ Bw, int K) {
    __shared__ __align__(16) float As[16][128];
    __shared__ __align__(16) float Bs[16][128];
    const float* A; float* C; int lda, ldc;
    if (mode == 0) { A = g_x2; lda = DD;  C = g_xz;  ldc = 2*DI; }
    else           { A = g_y;  lda = DI;  C = g_out; ldc = DD;   }
    int bm0 = blockIdx.y * 128, bn0 = blockIdx.x * 128;
    int tid = threadIdx.x;
    int lr = tid >> 2, lk = (tid & 3) << 2;
    int tr = tid >> 4, tc = tid & 15;
    float acc[8][8];
    #pragma unroll
    for (int i = 0; i < 8; i++)
        #pragma unroll
        for (int j = 0; j < 8; j++) acc[i][j] = 0.0f;
    for (int kk = 0; kk < K; kk += 16) {
        float4 a0 = *(const float4*)&A [(size_t)(bm0+lr)*lda + kk + lk];
        float4 a1 = *(const float4*)&A [(size_t)(bm0+64+lr)*lda + kk + lk];
        float4 b0 = *(const float4*)&Bw[(size_t)(bn0+lr)*K + kk + lk];
        float4 b1 = *(const float4*)&Bw[(size_t)(bn0+64+lr)*K + kk + lk];
        __syncthreads();
        As[lk+0][lr] = a0.x; As[lk+1][lr] = a0.y; As[lk+2][lr] = a0.z; As[lk+3][lr] = a0.w;
        As[lk+0][64+lr] = a1.x; As[lk+1][64+lr] = a1.y; As[lk+2][64+lr] = a1.z; As[lk+3][64+lr] = a1.w;
        Bs[lk+0][lr] = b0.x; Bs[lk+1][lr] = b0.y; Bs[lk+2][lr] = b0.z; Bs[lk+3][lr] = b0.w;
        Bs[lk+0][64+lr] = b1.x; Bs[lk+1][64+lr] = b1.y; Bs[lk+2][64+lr] = b1.z; Bs[lk+3][64+lr] = b1.w;
        __syncthreads();
        #pragma unroll
        for (int k = 0; k < 16; k++) {
            float ra[8], rb[8];
            *(float4*)&ra[0] = *(const float4*)&As[k][tr*4];
            *(float4*)&ra[4] = *(const float4*)&As[k][64 + tr*4];
            *(float4*)&rb[0] = *(const float4*)&Bs[k][tc*4];
            *(float4*)&rb[4] = *(const float4*)&Bs[k][64 + tc*4];
            #pragma unroll
            for (int i = 0; i < 8; i++)
                #pragma unroll
                for (int j = 0; j < 8; j++) acc[i][j] += ra[i]*rb[j];
        }
    }
    #pragma unroll
    for (int i = 0; i < 8; i++) {
        int r = (i < 4) ? (tr*4 + i) : (64 + tr*4 + i - 4);
        #pragma unroll
        for (int j = 0; j < 8; j++) {
            int cc = (j < 4) ? (tc*4 + j) : (64 + tc*4 + j - 4);
            C[(size_t)(bm0 + r)*ldc + bn0 + cc] = acc[i][j];
        }
    }
}

// ---------------- mamba: causal depthwise conv + silu ----------------
__global__ void k_convsilu(const float* __restrict__ cw, const float* __restrict__ cb) {
    int idx = blockIdx.x * blockDim.x + threadIdx.x;
    if (idx >= BT*DI) return;
    int c = idx & (DI-1);
    int t = (idx >> 8) & (TT-1);
    int b = idx >> 16;
    float acc = cb[c];
    #pragma unroll
    for (int j = 0; j < DCV; j++) {
        int tt = t - 3 + j;
        if (tt >= 0) acc += cw[c*DCV + j] * g_xz[(size_t)(b*TT + tt)*(2*DI) + c];
    }
    g_xc[idx] = acc / (1.0f + __expf(-acc));
}

// ---------------- mamba: dbl = xc @ xproj^T, fused dt ----------------
__global__ void k_dblt(const float* __restrict__ xp,
                       const float* __restrict__ dtw, const float* __restrict__ dtb) {
    __shared__ float sx[32][DI+1];
    __shared__ float sd[32][RKD];
    int t0 = blockIdx.x * 32;
    int tid = threadIdx.x;
    for (int i = tid; i < 32*DI; i += 256) {
        int tt = i >> 8, c = i & (DI-1);
        sx[tt][c] = g_xc[(size_t)(t0 + tt)*DI + c];
    }
    __syncthreads();
    for (int o = tid; o < 32*40; o += 256) {
        int tt = o & 31, k = o >> 5;
        const float* wrow = xp + k*DI;
        float acc = 0.0f;
        #pragma unroll 8
        for (int c = 0; c < DI; c++) acc += wrow[c] * sx[tt][c];
        if (k < RKD) sd[tt][k] = acc;
        else g_dbl[(size_t)(t0 + tt)*40 + k] = acc;
    }
    __syncthreads();
    {
        int c = tid;   // 0..255
        float wreg[RKD];
        #pragma unroll
        for (int r = 0; r < RKD; r++) wreg[r] = dtw[c*RKD + r];
        float bb = dtb[c];
        for (int tt = 0; tt < 32; tt++) {
            float acc = bb;
            #pragma unroll
            for (int r = 0; r < RKD; r++) acc += wreg[r] * sd[tt][r];
            g_dt[(size_t)(t0 + tt)*DI + c] = (acc > 20.0f) ? acc : log1pf(__expf(acc));
        }
    }
}

// ---------------- mamba: selective scan + gate ----------------
__global__ void k_scan(const float* __restrict__ Alog, const float* __restrict__ Dp) {
    __shared__ float sBC[TT][32];
    int b = blockIdx.y;
    int c = blockIdx.x * blockDim.x + threadIdx.x;
    for (int i = threadIdx.x; i < TT*32; i += blockDim.x) {
        int tt = i >> 5, j = i & 31;
        sBC[tt][j] = g_dbl[(size_t)(b*TT + tt)*40 + 8 + j];
    }
    __syncthreads();
    float Av[DSN];
    #pragma unroll
    for (int s = 0; s < DSN; s++) Av[s] = -__expf(Alog[c*DSN + s]);
    float A0 = Av[0];
    bool structured = true;
    #pragma unroll
    for (int s = 0; s < DSN; s++)
        if (fabsf(Av[s] - (float)(s+1)*A0) > 1e-4f * fabsf(Av[s])) structured = false;
    float h[DSN];
    #pragma unroll
    for (int s = 0; s < DSN; s++) h[s] = 0.0f;
    float dpc = Dp[c];
    for (int t = 0; t < TT; t++) {
        size_t bt = (size_t)(b*TT + t);
        float dtv = g_dt[bt*DI + c];
        float xcv = g_xc[bt*DI + c];
        float zv  = g_xz[bt*(2*DI) + DI + c];
        float dtxc = dtv * xcv;
        float y = 0.0f;
        if (structured) {
            float r = __expf(dtv * A0);
            float p = 1.0f;
            #pragma unroll
            for (int s = 0; s < DSN; s++) {
                p *= r;
                h[s] = p*h[s] + dtxc*sBC[t][s];
                y += h[s]*sBC[t][16+s];
            }
        } else {
            #pragma unroll
            for (int s = 0; s < DSN; s++) {
                float dA = __expf(dtv * Av[s]);
                h[s] = dA*h[s] + dtxc*sBC[t][s];
                y += h[s]*sBC[t][16+s];
            }
        }
        float yv = y + dpc*xcv;
        yv = yv * (zv / (1.0f + __expf(-zv)));
        g_y[bt*DI + c] = yv;
    }
}

// ---------------- residual + layernorm (in place on g_x2) ----------------
__global__ void k_ln(const float* __restrict__ g, const float* __restrict__ bta) {
    __shared__ float red[4];
    int bt = blockIdx.x, d = threadIdx.x;
    float v = g_x2[(size_t)bt*DD + d] + g_out[(size_t)bt*DD + d];
    float s = v;
    #pragma unroll
    for (int o = 16; o > 0; o >>= 1) s += __shfl_xor_sync(0xffffffffu, s, o);
    if ((d & 31) == 0) red[d >> 5] = s;
    __syncthreads();
    float mean = (red[0] + red[1] + red[2] + red[3]) * (1.0f/DD);
    float dv = v - mean;
    float q = dv * dv;
    #pragma unroll
    for (int o = 16; o > 0; o >>= 1) q += __shfl_xor_sync(0xffffffffu, q, o);
    __syncthreads();
    if ((d & 31) == 0) red[d >> 5] = q;
    __syncthreads();
    float var = (red[0] + red[1] + red[2] + red[3]) * (1.0f/DD);
    g_x2[(size_t)bt*DD + d] = dv * rsqrtf(var + 1e-5f) * g[d] + bta[d];
}

// ---------------- xflat transpose into d_out ----------------
__global__ void k_xflat2(float* __restrict__ out) {
    __shared__ float sm[32][257];
    int b = blockIdx.x, d0 = blockIdx.y * 32;
    int tid = threadIdx.x;
    int tb = tid >> 5, dd = tid & 31;
    for (int t = tb; t < TT; t += 8)
        sm[dd][t] = g_x2[(size_t)(b*TT + t)*DD + d0 + dd];
    __syncthreads();
    for (int dd2 = 0; dd2 < 32; dd2++)
        out[(size_t)b*(DD*TT) + (d0+dd2)*TT + tid] = sm[dd2][tid];
}

// ---------------- pred head ----------------
__global__ void k_pred(const float* __restrict__ xflat, const float* __restrict__ fcw,
                       const float* __restrict__ fcb, float* __restrict__ pred) {
    __shared__ float red[8];
    int c = blockIdx.x, b = blockIdx.y, tid = threadIdx.x;
    const float4* x4 = (const float4*)(xflat + (size_t)b * (DD*TT));
    const float4* w4 = (const float4*)(fcw + (size_t)c * (DD*TT));
    float s = 0.0f;
    for (int i = tid; i < DD*TT/4; i += blockDim.x) {
        float4 a = x4[i], w = w4[i];
        s += a.x*w.x + a.y*w.y + a.z*w.z + a.w*w.w;
    }
    #pragma unroll
    for (int o = 16; o > 0; o >>= 1) s += __shfl_xor_sync(0xffffffffu, s, o);
    if ((tid & 31) == 0) red[tid >> 5] = s;
    __syncthreads();
    if (tid == 0) {
        float tot = 0.0f;
        for (int i = 0; i < (int)(blockDim.x >> 5); i++) tot += red[i];
        pred[b*CC + c] = tot + fcb[c];
    }
}

// ---------------- launch ----------------
extern "C" void kernel_launch(void* const* d_in, const int* in_sizes, int n_in,
                              void* d_out, int out_size) {
    const float* inputs    = (const float*)d_in[0];
    const float* emb_w     = (const float*)d_in[1];
    const float* emb_b     = (const float*)d_in[2];
    const float* blk_dw_w  = (const float*)d_in[3];
    const float* blk_dw_b  = (const float*)d_in[4];
    const float* blk_pw_w  = (const float*)d_in[5];
    const float* blk_pw_b  = (const float*)d_in[6];
    const float* blk_se_w1 = (const float*)d_in[7];
    const float* blk_se_b1 = (const float*)d_in[8];
    const float* blk_se_w2 = (const float*)d_in[9];
    const float* blk_se_b2 = (const float*)d_in[10];
    const float* mam_in_w  = (const float*)d_in[11];
    const float* mam_conv_w= (const float*)d_in[12];
    const float* mam_conv_b= (const float*)d_in[13];
    const float* mam_xproj = (const float*)d_in[14];
    const float* mam_dt_w  = (const float*)d_in[15];
    const float* mam_dt_b  = (const float*)d_in[16];
    const float* mam_Alog  = (const float*)d_in[17];
    const float* mam_D     = (const float*)d_in[18];
    const float* mam_out_w = (const float*)d_in[19];
    const float* ln_g      = (const float*)d_in[20];
    const float* ln_b      = (const float*)d_in[21];
    const float* fc_w      = (const float*)d_in[22];
    const float* fc_b      = (const float*)d_in[23];
    float* out = (float*)d_out;

    float *uA, *uB, *wA, *wB, *s2, *aa;
    cudaGetSymbolAddress((void**)&uA, g_uA);
    cudaGetSymbolAddress((void**)&uB, g_uB);
    cudaGetSymbolAddress((void**)&wA, g_wA);
    cudaGetSymbolAddress((void**)&wB, g_wB);
    cudaGetSymbolAddress((void**)&s2, g_s2);
    cudaGetSymbolAddress((void**)&aa, g_a);

    k_emb<<<BMR, 256>>>(inputs, emb_w, emb_b);

    // block 0: read uA -> wA (no apply)
    k_block<<<dim3(2, BMR), 256>>>(uA, wA, aa, uB, wA, s2,
        blk_dw_w + 0*DD*KC, blk_dw_b + 0*DD, blk_pw_w + 0*DD*DD, blk_pw_b + 0*DD, 0);
    k_se<<<BMR, DD>>>(blk_se_w1 + 0*DR*DD, blk_se_b1 + 0*DR, blk_se_w2 + 0*DD*DR, blk_se_b2 + 0*DD);
    // block 1: read uA,wA,a -> u1 into uB, w1 into wB
    k_block<<<dim3(2, BMR), 256>>>(uA, wA, aa, uB, wB, s2,
        blk_dw_w + 1*DD*KC, blk_dw_b + 1*DD, blk_pw_w + 1*DD*DD, blk_pw_b + 1*DD, 1);
    k_se<<<BMR, DD>>>(blk_se_w1 + 1*DR*DD, blk_se_b1 + 1*DR, blk_se_w2 + 1*DD*DR, blk_se_b2 + 1*DD);
    // block 2: read uB,wB,a -> u2 into uA, w2 into wA
    k_block<<<dim3(2, BMR), 256>>>(uB, wB, aa, uA, wA, s2,
        blk_dw_w + 2*DD*KC, blk_dw_b + 2*DD, blk_pw_w + 2*DD*DD, blk_pw_b + 2*DD, 1);
    k_se<<<BMR, DD>>>(blk_se_w1 + 2*DR*DD, blk_se_b1 + 2*DR, blk_se_w2 + 2*DD*DR, blk_se_b2 + 2*DD);

    // final apply + sensor mean + layout change
    k_smean2<<<dim3(NB, DD/32), 256>>>(uA, wA, aa);

    for (int i = 0; i < NMB; i++) {
        k_gemm_nt<<<dim3(4, BT/128), 256>>>(0, mam_in_w + (size_t)i*2*DI*DD, DD);
        k_convsilu<<<(BT*DI)/256, 256>>>(mam_conv_w + i*DI*DCV, mam_conv_b + i*DI);
        k_dblt<<<BT/32, 256>>>(mam_xproj + (size_t)i*40*DI, mam_dt_w + i*DI*RKD, mam_dt_b + i*DI);
        k_scan<<<dim3(DI/128, NB), 128>>>(mam_Alog + i*DI*DSN, mam_D + i*DI);
        k_gemm_nt<<<dim3(1, BT/128), 256>>>(1, mam_out_w + (size_t)i*DD*DI, DI);
        k_ln<<<BT, DD>>>(ln_g + i*DD, ln_b + i*DD);
    }

    k_xflat2<<<dim3(NB, DD/32), 256>>>(out);
    k_pred<<<dim3(CC, NB), 256>>>(out, fc_w, fc_b, out + (size_t)NB*DD*TT);
}